// round 8
// baseline (speedup 1.0000x reference)
#include <cuda_runtime.h>
#include <cuda_bf16.h>
#include <cstdint>
#include <math.h>

#define BATCH 8
#define CH 512
#define HW 9216          // 96*96
#define KCODE 32
#define NCLASS 19
#define EPS 1e-5f

// ---------------- scratch (device globals; no allocation) ----------------
__device__ float g_X[(size_t)BATCH * HW * CH];   // (b, n, c) post conv+bn+relu
__device__ float g_G[BATCH * KCODE * CH];        // sum_n A[b,n,k] * X[b,n,c]
__device__ float g_Asum[BATCH * KCODE];
__device__ float g_en[BATCH * CH];
__device__ float g_gamma[BATCH * CH];

// ---------------- packed f32x2 FMA (sm_100+) ----------------
__device__ __forceinline__ float2 ffma2(float2 a, float2 b, float2 c) {
    unsigned long long ua = *(unsigned long long*)&a;
    unsigned long long ub = *(unsigned long long*)&b;
    unsigned long long uc = *(unsigned long long*)&c;
    unsigned long long ud;
    asm("fma.rn.f32x2 %0, %1, %2, %3;" : "=l"(ud) : "l"(ua), "l"(ub), "l"(uc));
    return *(float2*)&ud;
}

// bf16 mma m16n8k16, fp32 accumulate
#define MMA_BF16(d, a, b0_, b1_)                                            \
    asm volatile("mma.sync.aligned.m16n8k16.row.col.f32.bf16.bf16.f32 "     \
        "{%0,%1,%2,%3}, {%4,%5,%6,%7}, {%8,%9}, {%0,%1,%2,%3};"             \
        : "+f"((d)[0]), "+f"((d)[1]), "+f"((d)[2]), "+f"((d)[3])            \
        : "r"((a)[0]), "r"((a)[1]), "r"((a)[2]), "r"((a)[3]),               \
          "r"(b0_), "r"(b1_))

// ---------------- K0: zero accumulators ----------------
__global__ void k_zero() {
    int i = blockIdx.x * blockDim.x + threadIdx.x;
    if (i < BATCH * KCODE * CH) g_G[i] = 0.f;
    if (i < BATCH * KCODE) g_Asum[i] = 0.f;
}

// ---------------- K1: conv(1x1) via bf16 split mma + BN2 + ReLU ----------------
// out[o,n] = sum_c W[o,c] * x[b,c,n]. fp32 -> (hi,lo) bf16 split in smem;
// acc += Ah*Bh + Ah*Bl + Al*Bh (lo*lo dropped, ~9e-5 rel).
// Block tile 128o x 128n, K-chunk 32. 8 warps: 4(m) x 2(n), warp tile 32o x 64n.
__global__ __launch_bounds__(256) void k_conv(
    const float* __restrict__ W, const float* __restrict__ x,
    const float* __restrict__ bn2w, const float* __restrict__ bn2b,
    const float* __restrict__ bn2m, const float* __restrict__ bn2v)
{
    const int b = blockIdx.z;
    const float* Bx = x + (size_t)b * CH * HW;      // [c][n]
    float* Xo = g_X + (size_t)b * HW * CH;          // [n][o]
    const int oB = blockIdx.y * 128;
    const int nB = blockIdx.x * 128;

    // padded stride 34 halfwords: keeps b32 pair loads 4B-aligned, spreads banks
    __shared__ unsigned short Ah[128][34], Al[128][34];   // [o][k]
    __shared__ unsigned short Bh[128][34], Bl[128][34];   // [n][k]

    const int tid = threadIdx.x;
    const int lane = tid & 31, wid = tid >> 5;
    const int wm = wid >> 1, wn = wid & 1;          // warp grid 4x2
    const int oW = wm * 32, nW = wn * 64;
    const int r = lane >> 2, q2 = (lane & 3) * 2;

    float acc[2][8][4];
    #pragma unroll
    for (int mi = 0; mi < 2; mi++)
        #pragma unroll
        for (int ni = 0; ni < 8; ni++)
            #pragma unroll
            for (int j = 0; j < 4; j++) acc[mi][ni][j] = 0.f;

    for (int k0 = 0; k0 < CH; k0 += 32) {
        // ---- stage A tile (W[oB..+128][k0..+32]) with hi/lo split ----
        #pragma unroll
        for (int t = 0; t < 4; t++) {
            int idx = tid + t * 256;                 // 0..1023
            int row = idx >> 3, c4 = (idx & 7) * 4;
            float4 v = *(const float4*)&W[(size_t)(oB + row) * CH + k0 + c4];
            float vv[4] = { v.x, v.y, v.z, v.w };
            #pragma unroll
            for (int j = 0; j < 4; j++) {
                __nv_bfloat16 h = __float2bfloat16(vv[j]);
                float lo = vv[j] - __bfloat162float(h);
                Ah[row][c4 + j] = __bfloat16_as_ushort(h);
                Al[row][c4 + j] = __bfloat16_as_ushort(__float2bfloat16(lo));
            }
        }
        // ---- stage B tile transposed: Bs[n][k] = x[k][n] ----
        #pragma unroll
        for (int t = 0; t < 4; t++) {
            int c = (tid >> 5) + t * 8;              // k row 0..31
            int n4 = lane * 4;                       // coalesced along n
            float4 v = *(const float4*)&Bx[(size_t)(k0 + c) * HW + nB + n4];
            float vv[4] = { v.x, v.y, v.z, v.w };
            #pragma unroll
            for (int j = 0; j < 4; j++) {
                __nv_bfloat16 h = __float2bfloat16(vv[j]);
                float lo = vv[j] - __bfloat162float(h);
                Bh[n4 + j][c] = __bfloat16_as_ushort(h);
                Bl[n4 + j][c] = __bfloat16_as_ushort(__float2bfloat16(lo));
            }
        }
        __syncthreads();

        #pragma unroll
        for (int s = 0; s < 32; s += 16) {
            uint32_t ah[2][4], al[2][4];
            #pragma unroll
            for (int mi = 0; mi < 2; mi++) {
                int ro = oW + mi * 16 + r;
                ah[mi][0] = *(const uint32_t*)&Ah[ro][s + q2];
                ah[mi][1] = *(const uint32_t*)&Ah[ro + 8][s + q2];
                ah[mi][2] = *(const uint32_t*)&Ah[ro][s + q2 + 8];
                ah[mi][3] = *(const uint32_t*)&Ah[ro + 8][s + q2 + 8];
                al[mi][0] = *(const uint32_t*)&Al[ro][s + q2];
                al[mi][1] = *(const uint32_t*)&Al[ro + 8][s + q2];
                al[mi][2] = *(const uint32_t*)&Al[ro][s + q2 + 8];
                al[mi][3] = *(const uint32_t*)&Al[ro + 8][s + q2 + 8];
            }
            #pragma unroll
            for (int ni = 0; ni < 8; ni++) {
                int nc = nW + ni * 8 + r;
                uint32_t bh0 = *(const uint32_t*)&Bh[nc][s + q2];
                uint32_t bh1 = *(const uint32_t*)&Bh[nc][s + q2 + 8];
                uint32_t bl0 = *(const uint32_t*)&Bl[nc][s + q2];
                uint32_t bl1 = *(const uint32_t*)&Bl[nc][s + q2 + 8];
                #pragma unroll
                for (int mi = 0; mi < 2; mi++) {
                    MMA_BF16(acc[mi][ni], ah[mi], bh0, bh1);
                    MMA_BF16(acc[mi][ni], ah[mi], bl0, bl1);
                    MMA_BF16(acc[mi][ni], al[mi], bh0, bh1);
                }
            }
        }
        __syncthreads();
    }

    // ---- epilogue: BN + ReLU, write X[n][o] ----
    #pragma unroll
    for (int mi = 0; mi < 2; mi++) {
        int o0 = oB + oW + mi * 16 + r;              // rows o0 and o0+8
        float s0 = bn2w[o0] * rsqrtf(bn2v[o0] + EPS);
        float bi0 = bn2b[o0] - bn2m[o0] * s0;
        float s1 = bn2w[o0 + 8] * rsqrtf(bn2v[o0 + 8] + EPS);
        float bi1 = bn2b[o0 + 8] - bn2m[o0 + 8] * s1;
        #pragma unroll
        for (int ni = 0; ni < 8; ni++) {
            int n = nB + nW + ni * 8 + q2;
            Xo[(size_t)n * CH + o0]           = fmaxf(acc[mi][ni][0] * s0 + bi0, 0.f);
            Xo[(size_t)(n + 1) * CH + o0]     = fmaxf(acc[mi][ni][1] * s0 + bi0, 0.f);
            Xo[(size_t)n * CH + o0 + 8]       = fmaxf(acc[mi][ni][2] * s1 + bi1, 0.f);
            Xo[(size_t)(n + 1) * CH + o0 + 8] = fmaxf(acc[mi][ni][3] * s1 + bi1, 0.f);
        }
    }
}

// ---------------- K2: soft assignment + aggregation ----------------
__global__ __launch_bounds__(256) void k_encode(
    const float* __restrict__ codewords, const float* __restrict__ scale)
{
    const int b = blockIdx.y;
    const int n0 = blockIdx.x * 64;
    const float* Xg = g_X + (size_t)b * HW * CH + (size_t)n0 * CH;
    const int tid = threadIdx.x;

    __shared__ float Xs[64][68];    // 64-c chunk, padded
    __shared__ float cws[64][32];   // [c][k] chunk
    __shared__ float sls[64][33];
    __shared__ float Aw[64][32];    // softmax weights
    __shared__ float x2s[64];
    __shared__ float c2s[32];

    const int pix = tid >> 2;          // 0..63
    const int kg = (tid & 3) * 8;      // k base for xc
    float2 xc2[4];
    #pragma unroll
    for (int q = 0; q < 4; q++) xc2[q] = make_float2(0.f, 0.f);
    float x2acc = 0.f;
    float c2acc = 0.f;

    const int pr = tid >> 2, ccw = (tid & 3) * 16;
    const int kld = tid & 31, ccb = (tid >> 5) * 8;

    for (int c0 = 0; c0 < CH; c0 += 64) {
        #pragma unroll
        for (int q = 0; q < 4; q++)
            *(float4*)&Xs[pr][ccw + q * 4] =
                *(const float4*)&Xg[(size_t)pr * CH + c0 + ccw + q * 4];
        #pragma unroll
        for (int q = 0; q < 8; q++)
            cws[ccb + q][kld] = codewords[kld * CH + c0 + ccb + q];
        __syncthreads();

        if (tid < 32) {
            #pragma unroll 8
            for (int cc = 0; cc < 64; cc++) { float v = cws[cc][tid]; c2acc += v * v; }
        }
        #pragma unroll 4
        for (int cc = 0; cc < 64; cc++) {
            float xr = Xs[pix][cc];
            if ((tid & 3) == 0) x2acc += xr * xr;
            float2 xp = make_float2(xr, xr);
            float4 cv0 = *(const float4*)&cws[cc][kg];
            float4 cv1 = *(const float4*)&cws[cc][kg + 4];
            xc2[0] = ffma2(xp, make_float2(cv0.x, cv0.y), xc2[0]);
            xc2[1] = ffma2(xp, make_float2(cv0.z, cv0.w), xc2[1]);
            xc2[2] = ffma2(xp, make_float2(cv1.x, cv1.y), xc2[2]);
            xc2[3] = ffma2(xp, make_float2(cv1.z, cv1.w), xc2[3]);
        }
        __syncthreads();
    }

    if ((tid & 3) == 0) x2s[pix] = x2acc;
    if (tid < 32) c2s[tid] = c2acc;
    __syncthreads();

    {
        float x2v = x2s[pix];
        float xcv[8] = { xc2[0].x, xc2[0].y, xc2[1].x, xc2[1].y,
                         xc2[2].x, xc2[2].y, xc2[3].x, xc2[3].y };
        #pragma unroll
        for (int kk = 0; kk < 8; kk++) {
            int k = kg + kk;
            sls[pix][k] = scale[k] * (x2v - 2.f * xcv[kk] + c2s[k]);
        }
    }
    __syncthreads();

    // softmax per pixel (K=32)
    if (tid < 64) {
        float m = -1e30f;
        #pragma unroll
        for (int k = 0; k < 32; k++) m = fmaxf(m, sls[tid][k]);
        float s = 0.f;
        #pragma unroll
        for (int k = 0; k < 32; k++) {
            float e = expf(sls[tid][k] - m);
            Aw[tid][k] = e;
            s += e;
        }
        float inv = 1.f / s;
        #pragma unroll
        for (int k = 0; k < 32; k++) Aw[tid][k] *= inv;
    }
    __syncthreads();

    if (tid < 32) {
        float s = 0.f;
        #pragma unroll 8
        for (int p = 0; p < 64; p++) s += Aw[p][tid];
        atomicAdd(&g_Asum[b * KCODE + tid], s);
    }

    // G += A^T X  (per c-chunk)
    const int k4 = (tid & 7) * 4;
    const int dl = (tid >> 3) * 2;
    for (int c0 = 0; c0 < CH; c0 += 64) {
        __syncthreads();
        #pragma unroll
        for (int q = 0; q < 4; q++)
            *(float4*)&Xs[pr][ccw + q * 4] =
                *(const float4*)&Xg[(size_t)pr * CH + c0 + ccw + q * 4];
        __syncthreads();

        float2 acc[4];
        #pragma unroll
        for (int i = 0; i < 4; i++) acc[i] = make_float2(0.f, 0.f);
        #pragma unroll 4
        for (int p = 0; p < 64; p++) {
            float4 a4 = *(const float4*)&Aw[p][k4];
            float2 xv = *(const float2*)&Xs[p][dl];
            acc[0] = ffma2(make_float2(a4.x, a4.x), xv, acc[0]);
            acc[1] = ffma2(make_float2(a4.y, a4.y), xv, acc[1]);
            acc[2] = ffma2(make_float2(a4.z, a4.z), xv, acc[2]);
            acc[3] = ffma2(make_float2(a4.w, a4.w), xv, acc[3]);
        }
        #pragma unroll
        for (int i = 0; i < 4; i++) {
            float* gp = &g_G[((size_t)b * KCODE + k4 + i) * CH + c0 + dl];
            atomicAdd(gp, acc[i].x);
            atomicAdd(gp + 1, acc[i].y);
        }
    }
}

// ---------------- K3: E = G - Asum*cw, BN1 + ReLU, mean over K -> en ----------------
__global__ void k_en(const float* __restrict__ codewords,
                     const float* __restrict__ bn1w, const float* __restrict__ bn1b,
                     const float* __restrict__ bn1m, const float* __restrict__ bn1v)
{
    int idx = blockIdx.x * blockDim.x + threadIdx.x;
    if (idx >= BATCH * CH) return;
    int b = idx >> 9, d = idx & 511;
    float acc = 0.f;
    #pragma unroll
    for (int k = 0; k < KCODE; k++) {
        float s1 = bn1w[k] * rsqrtf(bn1v[k] + EPS);
        float bias = bn1b[k] - bn1m[k] * s1;
        float e = g_G[((size_t)b * KCODE + k) * CH + d]
                - g_Asum[b * KCODE + k] * codewords[k * CH + d];
        acc += fmaxf(e * s1 + bias, 0.f);
    }
    g_en[idx] = acc * (1.f / KCODE);
}

// ---------------- K4: gamma = sigmoid(en @ fc_w^T + fc_b); se head ----------------
__global__ __launch_bounds__(512) void k_gate(
    const float* __restrict__ fc_w, const float* __restrict__ fc_b,
    const float* __restrict__ se_w, const float* __restrict__ se_b,
    float* __restrict__ out_se)
{
    const int b = blockIdx.x;
    const int t = threadIdx.x;
    __shared__ float ens[CH];
    ens[t] = g_en[b * CH + t];
    __syncthreads();

    float acc = fc_b[t];
    const float* wr = fc_w + (size_t)t * CH;
    #pragma unroll 4
    for (int d = 0; d < CH; d += 4) {
        float4 w4 = *(const float4*)&wr[d];
        acc += ens[d] * w4.x + ens[d + 1] * w4.y + ens[d + 2] * w4.z + ens[d + 3] * w4.w;
    }
    g_gamma[b * CH + t] = 1.f / (1.f + expf(-acc));

    if (t < NCLASS) {
        float a2 = se_b[t];
        const float* sr = se_w + (size_t)t * CH;
        #pragma unroll 4
        for (int d = 0; d < CH; d += 4) {
            float4 w4 = *(const float4*)&sr[d];
            a2 += ens[d] * w4.x + ens[d + 1] * w4.y + ens[d + 2] * w4.z + ens[d + 3] * w4.w;
        }
        out_se[b * NCLASS + t] = a2;
    }
}

// ---------------- K5: out = relu(x * (1 + gamma)) ----------------
__global__ void k_out(const float* __restrict__ x, float* __restrict__ out)
{
    size_t i4 = (size_t)blockIdx.x * blockDim.x + threadIdx.x;   // float4 index
    size_t i = i4 * 4;
    int bc = (int)(i / HW);                 // b*CH + c (HW % 4 == 0, uniform per vec)
    float g = 1.f + g_gamma[bc];
    float4 v = ((const float4*)x)[i4];
    v.x = fmaxf(v.x * g, 0.f);
    v.y = fmaxf(v.y * g, 0.f);
    v.z = fmaxf(v.z * g, 0.f);
    v.w = fmaxf(v.w * g, 0.f);
    ((float4*)out)[i4] = v;
}

// ---------------- launch ----------------
extern "C" void kernel_launch(void* const* d_in, const int* in_sizes, int n_in,
                              void* d_out, int out_size)
{
    const float* x      = (const float*)d_in[0];
    const float* conv_w = (const float*)d_in[1];
    const float* bn2w   = (const float*)d_in[2];
    const float* bn2b   = (const float*)d_in[3];
    const float* bn2m   = (const float*)d_in[4];
    const float* bn2v   = (const float*)d_in[5];
    const float* cw     = (const float*)d_in[6];
    const float* scale  = (const float*)d_in[7];
    const float* bn1w   = (const float*)d_in[8];
    const float* bn1b   = (const float*)d_in[9];
    const float* bn1m   = (const float*)d_in[10];
    const float* bn1v   = (const float*)d_in[11];
    const float* fc_w   = (const float*)d_in[12];
    const float* fc_b   = (const float*)d_in[13];
    const float* se_w   = (const float*)d_in[14];
    const float* se_b   = (const float*)d_in[15];

    float* out_main = (float*)d_out;                                  // B*C*H*W
    float* out_se   = out_main + (size_t)BATCH * CH * HW;             // B*NCLASS

    k_zero<<<(BATCH * KCODE * CH + 255) / 256 + 1, 256>>>();

    dim3 g1(HW / 128, CH / 128, BATCH);
    k_conv<<<g1, 256>>>(conv_w, x, bn2w, bn2b, bn2m, bn2v);

    dim3 g2(HW / 64, BATCH);
    k_encode<<<g2, 256>>>(cw, scale);

    k_en<<<(BATCH * CH + 255) / 256, 256>>>(cw, bn1w, bn1b, bn1m, bn1v);

    k_gate<<<BATCH, 512>>>(fc_w, fc_b, se_w, se_b, out_se);

    size_t n4 = (size_t)BATCH * CH * HW / 4;
    k_out<<<(unsigned)(n4 / 256), 256>>>(x, out_main);
}

// round 14
// speedup vs baseline: 1.0104x; 1.0104x over previous
#include <cuda_runtime.h>
#include <cuda_bf16.h>
#include <cstdint>
#include <math.h>

#define BATCH 8
#define CH 512
#define HW 9216          // 96*96
#define KCODE 32
#define NCLASS 19
#define EPS 1e-5f

// ---------------- scratch (device globals; no allocation) ----------------
__device__ float g_X[(size_t)BATCH * HW * CH];   // (b, n, c) post conv+bn+relu
__device__ float g_G[BATCH * KCODE * CH];        // sum_n A[b,n,k] * X[b,n,c]
__device__ float g_Asum[BATCH * KCODE];
__device__ float g_en[BATCH * CH];
__device__ float g_gamma[BATCH * CH];
// pre-split bf16 hi/lo operands for the conv GEMM
__device__ unsigned short g_Whi[CH * CH], g_Wlo[CH * CH];                 // [o][c]
__device__ unsigned short g_Xthi[(size_t)BATCH * HW * CH];                // [b][n][c]
__device__ unsigned short g_Xtlo[(size_t)BATCH * HW * CH];

// ---------------- packed f32x2 FMA (sm_100+) ----------------
__device__ __forceinline__ float2 ffma2(float2 a, float2 b, float2 c) {
    unsigned long long ua = *(unsigned long long*)&a;
    unsigned long long ub = *(unsigned long long*)&b;
    unsigned long long uc = *(unsigned long long*)&c;
    unsigned long long ud;
    asm("fma.rn.f32x2 %0, %1, %2, %3;" : "=l"(ud) : "l"(ua), "l"(ub), "l"(uc));
    return *(float2*)&ud;
}

// bf16 mma m16n8k16, fp32 accumulate
#define MMA_BF16(d, a, b0_, b1_)                                            \
    asm volatile("mma.sync.aligned.m16n8k16.row.col.f32.bf16.bf16.f32 "     \
        "{%0,%1,%2,%3}, {%4,%5,%6,%7}, {%8,%9}, {%0,%1,%2,%3};"             \
        : "+f"((d)[0]), "+f"((d)[1]), "+f"((d)[2]), "+f"((d)[3])            \
        : "r"((a)[0]), "r"((a)[1]), "r"((a)[2]), "r"((a)[3]),               \
          "r"(b0_), "r"(b1_))

// ---------------- K0: zero accumulators ----------------
__global__ void k_zero() {
    int i = blockIdx.x * blockDim.x + threadIdx.x;
    if (i < BATCH * KCODE * CH) g_G[i] = 0.f;
    if (i < BATCH * KCODE) g_Asum[i] = 0.f;
    if (i < BATCH * CH) g_en[i] = 0.f;
}

// ---------------- P1: split W -> hi/lo bf16 (once) ----------------
__global__ void k_prep_w(const float* __restrict__ W) {
    int i = blockIdx.x * blockDim.x + threadIdx.x;
    if (i >= CH * CH) return;
    float v = W[i];
    __nv_bfloat16 h = __float2bfloat16(v);
    g_Whi[i] = __bfloat16_as_ushort(h);
    g_Wlo[i] = __bfloat16_as_ushort(__float2bfloat16(v - __bfloat162float(h)));
}

// ---------------- P2: transpose + split x -> [b][n][c] hi/lo bf16 ----------------
// 32x32 tiles: read x[b][c][n] coalesced along n, write [b][n][c] coalesced along c.
__global__ __launch_bounds__(256) void k_prep_x(const float* __restrict__ x) {
    const int b = blockIdx.z;
    const int nB = blockIdx.x * 32;
    const int cB = blockIdx.y * 32;
    __shared__ float t[32][33];
    const int tx = threadIdx.x & 31, ty = threadIdx.x >> 5;   // ty 0..7
    const float* xb = x + (size_t)b * CH * HW;
    #pragma unroll
    for (int i = 0; i < 4; i++) {
        int c = cB + ty + i * 8;
        t[ty + i * 8][tx] = xb[(size_t)c * HW + nB + tx];
    }
    __syncthreads();
    unsigned short* oh = g_Xthi + (size_t)b * HW * CH;
    unsigned short* ol = g_Xtlo + (size_t)b * HW * CH;
    #pragma unroll
    for (int i = 0; i < 4; i++) {
        int n = nB + ty + i * 8;
        float v = t[tx][ty + i * 8];
        __nv_bfloat16 h = __float2bfloat16(v);
        size_t o = (size_t)n * CH + cB + tx;
        oh[o] = __bfloat16_as_ushort(h);
        ol[o] = __bfloat16_as_ushort(__float2bfloat16(v - __bfloat162float(h)));
    }
}

// ---------------- K1: conv(1x1) via bf16 split mma + BN2 + ReLU ----------------
// out[o,n] = sum_c W[o,c] * x[b,c,n]; acc += Ah*Bh + Ah*Bl + Al*Bh.
// Operands are pre-split bf16 (hi/lo) in global; staging is pure uint4 copy.
// Block tile 128o x 128n, K-chunk 32. 8 warps: 4(m) x 2(n), warp tile 32o x 64n.
__global__ __launch_bounds__(256) void k_conv(
    const float* __restrict__ bn2w, const float* __restrict__ bn2b,
    const float* __restrict__ bn2m, const float* __restrict__ bn2v)
{
    const int b = blockIdx.z;
    const unsigned short* Bxh = g_Xthi + (size_t)b * HW * CH;   // [n][c]
    const unsigned short* Bxl = g_Xtlo + (size_t)b * HW * CH;
    float* Xo = g_X + (size_t)b * HW * CH;                      // [n][o]
    const int oB = blockIdx.y * 128;
    const int nB = blockIdx.x * 128;

    // stride 40 halfwords (80B): rows 16B-aligned for uint4, conflict-free frags
    __shared__ __align__(16) unsigned short Ah[128][40], Al[128][40];   // [o][k]
    __shared__ __align__(16) unsigned short Bh[128][40], Bl[128][40];   // [n][k]

    const int tid = threadIdx.x;
    const int lane = tid & 31, wid = tid >> 5;
    const int wm = wid >> 1, wn = wid & 1;          // warp grid 4x2
    const int oW = wm * 32, nW = wn * 64;
    const int r = lane >> 2, q2 = (lane & 3) * 2;

    float acc[2][8][4];
    #pragma unroll
    for (int mi = 0; mi < 2; mi++)
        #pragma unroll
        for (int ni = 0; ni < 8; ni++)
            #pragma unroll
            for (int j = 0; j < 4; j++) acc[mi][ni][j] = 0.f;

    for (int k0 = 0; k0 < CH; k0 += 32) {
        // stage: 128 rows x 32 halfs per matrix = 512 uint4 slots, 2 per thread
        #pragma unroll
        for (int it = 0; it < 2; it++) {
            int slot = tid + it * 256;               // 0..511
            int row = slot >> 2, q8 = (slot & 3) * 8;
            size_t ga = (size_t)(oB + row) * CH + k0 + q8;
            size_t gb = (size_t)(nB + row) * CH + k0 + q8;
            *(uint4*)&Ah[row][q8] = *(const uint4*)&g_Whi[ga];
            *(uint4*)&Al[row][q8] = *(const uint4*)&g_Wlo[ga];
            *(uint4*)&Bh[row][q8] = *(const uint4*)&Bxh[gb];
            *(uint4*)&Bl[row][q8] = *(const uint4*)&Bxl[gb];
        }
        __syncthreads();

        #pragma unroll
        for (int s = 0; s < 32; s += 16) {
            uint32_t ah[2][4], al[2][4];
            #pragma unroll
            for (int mi = 0; mi < 2; mi++) {
                int ro = oW + mi * 16 + r;
                ah[mi][0] = *(const uint32_t*)&Ah[ro][s + q2];
                ah[mi][1] = *(const uint32_t*)&Ah[ro + 8][s + q2];
                ah[mi][2] = *(const uint32_t*)&Ah[ro][s + q2 + 8];
                ah[mi][3] = *(const uint32_t*)&Ah[ro + 8][s + q2 + 8];
                al[mi][0] = *(const uint32_t*)&Al[ro][s + q2];
                al[mi][1] = *(const uint32_t*)&Al[ro + 8][s + q2];
                al[mi][2] = *(const uint32_t*)&Al[ro][s + q2 + 8];
                al[mi][3] = *(const uint32_t*)&Al[ro + 8][s + q2 + 8];
            }
            #pragma unroll
            for (int ni = 0; ni < 8; ni++) {
                int nc = nW + ni * 8 + r;
                uint32_t bh0 = *(const uint32_t*)&Bh[nc][s + q2];
                uint32_t bh1 = *(const uint32_t*)&Bh[nc][s + q2 + 8];
                uint32_t bl0 = *(const uint32_t*)&Bl[nc][s + q2];
                uint32_t bl1 = *(const uint32_t*)&Bl[nc][s + q2 + 8];
                #pragma unroll
                for (int mi = 0; mi < 2; mi++) {
                    MMA_BF16(acc[mi][ni], ah[mi], bh0, bh1);
                    MMA_BF16(acc[mi][ni], ah[mi], bl0, bl1);
                    MMA_BF16(acc[mi][ni], al[mi], bh0, bh1);
                }
            }
        }
        __syncthreads();
    }

    // ---- epilogue: BN + ReLU, write X[n][o] ----
    #pragma unroll
    for (int mi = 0; mi < 2; mi++) {
        int o0 = oB + oW + mi * 16 + r;              // rows o0 and o0+8
        float s0 = bn2w[o0] * rsqrtf(bn2v[o0] + EPS);
        float bi0 = bn2b[o0] - bn2m[o0] * s0;
        float s1 = bn2w[o0 + 8] * rsqrtf(bn2v[o0 + 8] + EPS);
        float bi1 = bn2b[o0 + 8] - bn2m[o0 + 8] * s1;
        #pragma unroll
        for (int ni = 0; ni < 8; ni++) {
            int n = nB + nW + ni * 8 + q2;
            Xo[(size_t)n * CH + o0]           = fmaxf(acc[mi][ni][0] * s0 + bi0, 0.f);
            Xo[(size_t)(n + 1) * CH + o0]     = fmaxf(acc[mi][ni][1] * s0 + bi0, 0.f);
            Xo[(size_t)n * CH + o0 + 8]       = fmaxf(acc[mi][ni][2] * s1 + bi1, 0.f);
            Xo[(size_t)(n + 1) * CH + o0 + 8] = fmaxf(acc[mi][ni][3] * s1 + bi1, 0.f);
        }
    }
}

// ---------------- K2: soft assignment + aggregation ----------------
__global__ __launch_bounds__(256) void k_encode(
    const float* __restrict__ codewords, const float* __restrict__ scale)
{
    const int b = blockIdx.y;
    const int n0 = blockIdx.x * 64;
    const float* Xg = g_X + (size_t)b * HW * CH + (size_t)n0 * CH;
    const int tid = threadIdx.x;

    __shared__ float Xs[64][68];    // 64-c chunk, padded
    __shared__ float cws[64][32];   // [c][k] chunk
    __shared__ float sls[64][33];
    __shared__ float Aw[64][32];    // softmax weights
    __shared__ float x2s[64];
    __shared__ float c2s[32];

    const int pix = tid >> 2;          // 0..63
    const int kg = (tid & 3) * 8;      // k base for xc
    float2 xc2[4];
    #pragma unroll
    for (int q = 0; q < 4; q++) xc2[q] = make_float2(0.f, 0.f);
    float x2acc = 0.f;
    float c2acc = 0.f;

    const int pr = tid >> 2, ccw = (tid & 3) * 16;
    const int kld = tid & 31, ccb = (tid >> 5) * 8;

    for (int c0 = 0; c0 < CH; c0 += 64) {
        #pragma unroll
        for (int q = 0; q < 4; q++)
            *(float4*)&Xs[pr][ccw + q * 4] =
                *(const float4*)&Xg[(size_t)pr * CH + c0 + ccw + q * 4];
        #pragma unroll
        for (int q = 0; q < 8; q++)
            cws[ccb + q][kld] = codewords[kld * CH + c0 + ccb + q];
        __syncthreads();

        if (tid < 32) {
            #pragma unroll 8
            for (int cc = 0; cc < 64; cc++) { float v = cws[cc][tid]; c2acc += v * v; }
        }
        #pragma unroll 4
        for (int cc = 0; cc < 64; cc++) {
            float xr = Xs[pix][cc];
            if ((tid & 3) == 0) x2acc += xr * xr;
            float2 xp = make_float2(xr, xr);
            float4 cv0 = *(const float4*)&cws[cc][kg];
            float4 cv1 = *(const float4*)&cws[cc][kg + 4];
            xc2[0] = ffma2(xp, make_float2(cv0.x, cv0.y), xc2[0]);
            xc2[1] = ffma2(xp, make_float2(cv0.z, cv0.w), xc2[1]);
            xc2[2] = ffma2(xp, make_float2(cv1.x, cv1.y), xc2[2]);
            xc2[3] = ffma2(xp, make_float2(cv1.z, cv1.w), xc2[3]);
        }
        __syncthreads();
    }

    if ((tid & 3) == 0) x2s[pix] = x2acc;
    if (tid < 32) c2s[tid] = c2acc;
    __syncthreads();

    {
        float x2v = x2s[pix];
        float xcv[8] = { xc2[0].x, xc2[0].y, xc2[1].x, xc2[1].y,
                         xc2[2].x, xc2[2].y, xc2[3].x, xc2[3].y };
        #pragma unroll
        for (int kk = 0; kk < 8; kk++) {
            int k = kg + kk;
            sls[pix][k] = scale[k] * (x2v - 2.f * xcv[kk] + c2s[k]);
        }
    }
    __syncthreads();

    // softmax per pixel (K=32)
    if (tid < 64) {
        float m = -1e30f;
        #pragma unroll
        for (int k = 0; k < 32; k++) m = fmaxf(m, sls[tid][k]);
        float s = 0.f;
        #pragma unroll
        for (int k = 0; k < 32; k++) {
            float e = expf(sls[tid][k] - m);
            Aw[tid][k] = e;
            s += e;
        }
        float inv = 1.f / s;
        #pragma unroll
        for (int k = 0; k < 32; k++) Aw[tid][k] *= inv;
    }
    __syncthreads();

    if (tid < 32) {
        float s = 0.f;
        #pragma unroll 8
        for (int p = 0; p < 64; p++) s += Aw[p][tid];
        atomicAdd(&g_Asum[b * KCODE + tid], s);
    }

    // G += A^T X  (per c-chunk)
    const int k4 = (tid & 7) * 4;
    const int dl = (tid >> 3) * 2;
    for (int c0 = 0; c0 < CH; c0 += 64) {
        __syncthreads();
        #pragma unroll
        for (int q = 0; q < 4; q++)
            *(float4*)&Xs[pr][ccw + q * 4] =
                *(const float4*)&Xg[(size_t)pr * CH + c0 + ccw + q * 4];
        __syncthreads();

        float2 acc[4];
        #pragma unroll
        for (int i = 0; i < 4; i++) acc[i] = make_float2(0.f, 0.f);
        #pragma unroll 4
        for (int p = 0; p < 64; p++) {
            float4 a4 = *(const float4*)&Aw[p][k4];
            float2 xv = *(const float2*)&Xs[p][dl];
            acc[0] = ffma2(make_float2(a4.x, a4.x), xv, acc[0]);
            acc[1] = ffma2(make_float2(a4.y, a4.y), xv, acc[1]);
            acc[2] = ffma2(make_float2(a4.z, a4.z), xv, acc[2]);
            acc[3] = ffma2(make_float2(a4.w, a4.w), xv, acc[3]);
        }
        #pragma unroll
        for (int i = 0; i < 4; i++) {
            float* gp = &g_G[((size_t)b * KCODE + k4 + i) * CH + c0 + dl];
            atomicAdd(gp, acc[i].x);
            atomicAdd(gp + 1, acc[i].y);
        }
    }
}

// ---------------- K3: E = G - Asum*cw, BN1 + ReLU, partial mean -> en ----------------
// K split 4 ways across blocks; atomicAdd into zeroed g_en for better latency hiding.
__global__ void k_en(const float* __restrict__ codewords,
                     const float* __restrict__ bn1w, const float* __restrict__ bn1b,
                     const float* __restrict__ bn1m, const float* __restrict__ bn1v)
{
    int idx = blockIdx.x * blockDim.x + threadIdx.x;
    if (idx >= 4 * BATCH * CH) return;
    int kq = idx >> 12;                 // 0..3
    int rem = idx & (BATCH * CH - 1);
    int b = rem >> 9, d = rem & 511;
    float acc = 0.f;
    #pragma unroll
    for (int kk = 0; kk < 8; kk++) {
        int k = kq * 8 + kk;
        float s1 = bn1w[k] * rsqrtf(bn1v[k] + EPS);
        float bias = bn1b[k] - bn1m[k] * s1;
        float e = g_G[((size_t)b * KCODE + k) * CH + d]
                - g_Asum[b * KCODE + k] * codewords[k * CH + d];
        acc += fmaxf(e * s1 + bias, 0.f);
    }
    atomicAdd(&g_en[rem], acc * (1.f / KCODE));
}

// ---------------- K4: gamma = sigmoid(en @ fc_w^T + fc_b); se head ----------------
__global__ __launch_bounds__(512) void k_gate(
    const float* __restrict__ fc_w, const float* __restrict__ fc_b,
    const float* __restrict__ se_w, const float* __restrict__ se_b,
    float* __restrict__ out_se)
{
    const int b = blockIdx.x;
    const int t = threadIdx.x;
    __shared__ float ens[CH];
    ens[t] = g_en[b * CH + t];
    __syncthreads();

    float acc = fc_b[t];
    const float* wr = fc_w + (size_t)t * CH;
    #pragma unroll 4
    for (int d = 0; d < CH; d += 4) {
        float4 w4 = *(const float4*)&wr[d];
        acc += ens[d] * w4.x + ens[d + 1] * w4.y + ens[d + 2] * w4.z + ens[d + 3] * w4.w;
    }
    g_gamma[b * CH + t] = 1.f / (1.f + expf(-acc));

    if (t < NCLASS) {
        float a2 = se_b[t];
        const float* sr = se_w + (size_t)t * CH;
        #pragma unroll 4
        for (int d = 0; d < CH; d += 4) {
            float4 w4 = *(const float4*)&sr[d];
            a2 += ens[d] * w4.x + ens[d + 1] * w4.y + ens[d + 2] * w4.z + ens[d + 3] * w4.w;
        }
        out_se[b * NCLASS + t] = a2;
    }
}

// ---------------- K5: out = relu(x * (1 + gamma)) ----------------
__global__ void k_out(const float* __restrict__ x, float* __restrict__ out)
{
    size_t i4 = (size_t)blockIdx.x * blockDim.x + threadIdx.x;   // float4 index
    size_t i = i4 * 4;
    int bc = (int)(i / HW);                 // b*CH + c (HW % 4 == 0, uniform per vec)
    float g = 1.f + g_gamma[bc];
    float4 v = ((const float4*)x)[i4];
    v.x = fmaxf(v.x * g, 0.f);
    v.y = fmaxf(v.y * g, 0.f);
    v.z = fmaxf(v.z * g, 0.f);
    v.w = fmaxf(v.w * g, 0.f);
    ((float4*)out)[i4] = v;
}

// ---------------- launch ----------------
extern "C" void kernel_launch(void* const* d_in, const int* in_sizes, int n_in,
                              void* d_out, int out_size)
{
    const float* x      = (const float*)d_in[0];
    const float* conv_w = (const float*)d_in[1];
    const float* bn2w   = (const float*)d_in[2];
    const float* bn2b   = (const float*)d_in[3];
    const float* bn2m   = (const float*)d_in[4];
    const float* bn2v   = (const float*)d_in[5];
    const float* cw     = (const float*)d_in[6];
    const float* scale  = (const float*)d_in[7];
    const float* bn1w   = (const float*)d_in[8];
    const float* bn1b   = (const float*)d_in[9];
    const float* bn1m   = (const float*)d_in[10];
    const float* bn1v   = (const float*)d_in[11];
    const float* fc_w   = (const float*)d_in[12];
    const float* fc_b   = (const float*)d_in[13];
    const float* se_w   = (const float*)d_in[14];
    const float* se_b   = (const float*)d_in[15];

    float* out_main = (float*)d_out;                                  // B*C*H*W
    float* out_se   = out_main + (size_t)BATCH * CH * HW;             // B*NCLASS

    k_zero<<<(BATCH * KCODE * CH + 255) / 256 + 1, 256>>>();

    k_prep_w<<<(CH * CH + 255) / 256, 256>>>(conv_w);

    dim3 gp(HW / 32, CH / 32, BATCH);
    k_prep_x<<<gp, 256>>>(x);

    dim3 g1(HW / 128, CH / 128, BATCH);
    k_conv<<<g1, 256>>>(bn2w, bn2b, bn2m, bn2v);

    dim3 g2(HW / 64, BATCH);
    k_encode<<<g2, 256>>>(cw, scale);

    k_en<<<(4 * BATCH * CH + 255) / 256, 256>>>(cw, bn1w, bn1b, bn1m, bn1v);

    k_gate<<<BATCH, 512>>>(fc_w, fc_b, se_w, se_b, out_se);

    size_t n4 = (size_t)BATCH * CH * HW / 4;
    k_out<<<(unsigned)(n4 / 256), 256>>>(x, out_main);
}

// round 15
// speedup vs baseline: 1.0417x; 1.0309x over previous
#include <cuda_runtime.h>
#include <cuda_bf16.h>
#include <cstdint>
#include <math.h>

#define BATCH 8
#define CH 512
#define HW 9216          // 96*96
#define KCODE 32
#define NCLASS 19
#define EPS 1e-5f

// ---------------- scratch (device globals; no allocation) ----------------
__device__ float g_X[(size_t)BATCH * HW * CH];   // (b, n, c) post conv+bn+relu
__device__ float g_G[BATCH * KCODE * CH];        // sum_n A[b,n,k] * X[b,n,c]
__device__ float g_Asum[BATCH * KCODE];
__device__ float g_en[BATCH * CH];
__device__ float g_gamma[BATCH * CH];
// pre-split bf16 hi/lo operands for the conv GEMM
__device__ unsigned short g_Whi[CH * CH], g_Wlo[CH * CH];                 // [o][c]
__device__ unsigned short g_Xthi[(size_t)BATCH * HW * CH];                // [b][n][c]
__device__ unsigned short g_Xtlo[(size_t)BATCH * HW * CH];

// ---------------- packed f32x2 FMA (sm_100+) ----------------
__device__ __forceinline__ float2 ffma2(float2 a, float2 b, float2 c) {
    unsigned long long ua = *(unsigned long long*)&a;
    unsigned long long ub = *(unsigned long long*)&b;
    unsigned long long uc = *(unsigned long long*)&c;
    unsigned long long ud;
    asm("fma.rn.f32x2 %0, %1, %2, %3;" : "=l"(ud) : "l"(ua), "l"(ub), "l"(uc));
    return *(float2*)&ud;
}

// bf16 mma m16n8k16, fp32 accumulate
#define MMA_BF16(d, a, b0_, b1_)                                            \
    asm volatile("mma.sync.aligned.m16n8k16.row.col.f32.bf16.bf16.f32 "     \
        "{%0,%1,%2,%3}, {%4,%5,%6,%7}, {%8,%9}, {%0,%1,%2,%3};"             \
        : "+f"((d)[0]), "+f"((d)[1]), "+f"((d)[2]), "+f"((d)[3])            \
        : "r"((a)[0]), "r"((a)[1]), "r"((a)[2]), "r"((a)[3]),               \
          "r"(b0_), "r"(b1_))

__device__ __forceinline__ void ldsm_x4(uint32_t& r0, uint32_t& r1,
                                        uint32_t& r2, uint32_t& r3, uint32_t addr) {
    asm volatile("ldmatrix.sync.aligned.m8n8.x4.shared.b16 {%0,%1,%2,%3}, [%4];"
        : "=r"(r0), "=r"(r1), "=r"(r2), "=r"(r3) : "r"(addr));
}

__device__ __forceinline__ void cp16(uint32_t smem_dst, const void* gsrc) {
    asm volatile("cp.async.cg.shared.global [%0], [%1], 16;"
        :: "r"(smem_dst), "l"(gsrc));
}
#define CP_COMMIT() asm volatile("cp.async.commit_group;")
#define CP_WAIT1()  asm volatile("cp.async.wait_group 1;")
#define CP_WAIT0()  asm volatile("cp.async.wait_group 0;")

// ---------------- K0: zero accumulators ----------------
__global__ void k_zero() {
    int i = blockIdx.x * blockDim.x + threadIdx.x;
    if (i < BATCH * KCODE * CH) g_G[i] = 0.f;
    if (i < BATCH * KCODE) g_Asum[i] = 0.f;
    if (i < BATCH * CH) g_en[i] = 0.f;
}

// ---------------- P1: split W -> hi/lo bf16 (once) ----------------
__global__ void k_prep_w(const float* __restrict__ W) {
    int i = blockIdx.x * blockDim.x + threadIdx.x;
    if (i >= CH * CH) return;
    float v = W[i];
    __nv_bfloat16 h = __float2bfloat16(v);
    g_Whi[i] = __bfloat16_as_ushort(h);
    g_Wlo[i] = __bfloat16_as_ushort(__float2bfloat16(v - __bfloat162float(h)));
}

// ---------------- P2: transpose + split x -> [b][n][c] hi/lo bf16 ----------------
__global__ __launch_bounds__(256) void k_prep_x(const float* __restrict__ x) {
    const int b = blockIdx.z;
    const int nB = blockIdx.x * 32;
    const int cB = blockIdx.y * 32;
    __shared__ float t[32][33];
    const int tx = threadIdx.x & 31, ty = threadIdx.x >> 5;   // ty 0..7
    const float* xb = x + (size_t)b * CH * HW;
    #pragma unroll
    for (int i = 0; i < 4; i++) {
        int c = cB + ty + i * 8;
        t[ty + i * 8][tx] = xb[(size_t)c * HW + nB + tx];
    }
    __syncthreads();
    unsigned short* oh = g_Xthi + (size_t)b * HW * CH;
    unsigned short* ol = g_Xtlo + (size_t)b * HW * CH;
    #pragma unroll
    for (int i = 0; i < 4; i++) {
        int n = nB + ty + i * 8;
        float v = t[tx][ty + i * 8];
        __nv_bfloat16 h = __float2bfloat16(v);
        size_t o = (size_t)n * CH + cB + tx;
        oh[o] = __bfloat16_as_ushort(h);
        ol[o] = __bfloat16_as_ushort(__float2bfloat16(v - __bfloat162float(h)));
    }
}

// ---------------- K1: conv(1x1), bf16 split mma, cp.async double-buffer ----------
// out[o,n] = sum_c W[o,c]*x[b,c,n]; acc += Ah*Bh + Ah*Bl + Al*Bh.
// k-chunk 16, 2-stage pipeline; ldmatrix fragment loads; 2 CTAs/SM target.
#define KC 16
#define SSTR 24   // smem row stride in halfwords (48B): 16B-aligned, ldsm conflict-free
__global__ __launch_bounds__(256, 2) void k_conv(
    const float* __restrict__ bn2w, const float* __restrict__ bn2b,
    const float* __restrict__ bn2m, const float* __restrict__ bn2v)
{
    const int b = blockIdx.z;
    const unsigned short* Bxh = g_Xthi + (size_t)b * HW * CH;   // [n][c]
    const unsigned short* Bxl = g_Xtlo + (size_t)b * HW * CH;
    float* Xo = g_X + (size_t)b * HW * CH;                      // [n][o]
    const int oB = blockIdx.y * 128;
    const int nB = blockIdx.x * 128;

    __shared__ __align__(16) unsigned short Ah[2][128][SSTR], Al[2][128][SSTR];
    __shared__ __align__(16) unsigned short Bh[2][128][SSTR], Bl[2][128][SSTR];

    const int tid = threadIdx.x;
    const int lane = tid & 31, wid = tid >> 5;
    const int wm = wid >> 1, wn = wid & 1;          // warp grid 4x2
    const int oW = wm * 32, nW = wn * 64;
    const int r = lane >> 2, q2 = (lane & 3) * 2;
    const int lrow = lane & 15, lcol = (lane >> 4) * 8;   // ldmatrix lane mapping

    // staging: each thread does one 16B cp.async per matrix per chunk
    const int srow = tid >> 1, sq8 = (tid & 1) * 8;

    float acc[2][8][4];
    #pragma unroll
    for (int mi = 0; mi < 2; mi++)
        #pragma unroll
        for (int ni = 0; ni < 8; ni++)
            #pragma unroll
            for (int j = 0; j < 4; j++) acc[mi][ni][j] = 0.f;

    uint32_t sAh = (uint32_t)__cvta_generic_to_shared(&Ah[0][0][0]);
    uint32_t sAl = (uint32_t)__cvta_generic_to_shared(&Al[0][0][0]);
    uint32_t sBh = (uint32_t)__cvta_generic_to_shared(&Bh[0][0][0]);
    uint32_t sBl = (uint32_t)__cvta_generic_to_shared(&Bl[0][0][0]);
    const uint32_t bufB = 128 * SSTR * 2;            // bytes per buffer
    const uint32_t sdst = (srow * SSTR + sq8) * 2;   // byte offset within buffer

    #define STAGE(chunk, buf)                                                  \
        do {                                                                   \
            int k0_ = (chunk) * KC + sq8;                                      \
            cp16(sAh + (buf) * bufB + sdst, &g_Whi[(size_t)(oB + srow) * CH + k0_]); \
            cp16(sAl + (buf) * bufB + sdst, &g_Wlo[(size_t)(oB + srow) * CH + k0_]); \
            cp16(sBh + (buf) * bufB + sdst, &Bxh[(size_t)(nB + srow) * CH + k0_]);   \
            cp16(sBl + (buf) * bufB + sdst, &Bxl[(size_t)(nB + srow) * CH + k0_]);   \
        } while (0)

    STAGE(0, 0);
    CP_COMMIT();

    for (int c = 0; c < CH / KC; c++) {
        __syncthreads();                  // prior compute on target buf done
        if (c + 1 < CH / KC) {
            STAGE(c + 1, (c + 1) & 1);
            CP_COMMIT();
            CP_WAIT1();
        } else {
            CP_WAIT0();
        }
        __syncthreads();                  // staged data visible to all warps

        const int buf = c & 1;
        // A fragments: m16k16 per mi, hi and lo
        uint32_t ah[2][4], al[2][4];
        #pragma unroll
        for (int mi = 0; mi < 2; mi++) {
            uint32_t aoff = (uint32_t)(((oW + mi * 16 + lrow) * SSTR + lcol) * 2) + buf * bufB;
            ldsm_x4(ah[mi][0], ah[mi][1], ah[mi][2], ah[mi][3], sAh + aoff);
            ldsm_x4(al[mi][0], al[mi][1], al[mi][2], al[mi][3], sAl + aoff);
        }
        #pragma unroll
        for (int nip = 0; nip < 4; nip++) {          // 2 n-tiles per ldsm.x4
            uint32_t boff = (uint32_t)(((nW + nip * 16 + lrow) * SSTR + lcol) * 2) + buf * bufB;
            uint32_t bh0, bh1, bh2, bh3, bl0, bl1, bl2, bl3;
            ldsm_x4(bh0, bh1, bh2, bh3, sBh + boff);
            ldsm_x4(bl0, bl1, bl2, bl3, sBl + boff);
            #pragma unroll
            for (int mi = 0; mi < 2; mi++) {
                // ni = 2*nip  -> b regs {r0, r2};  ni = 2*nip+1 -> {r1, r3}
                MMA_BF16(acc[mi][2 * nip],     ah[mi], bh0, bh2);
                MMA_BF16(acc[mi][2 * nip],     ah[mi], bl0, bl2);
                MMA_BF16(acc[mi][2 * nip],     al[mi], bh0, bh2);
                MMA_BF16(acc[mi][2 * nip + 1], ah[mi], bh1, bh3);
                MMA_BF16(acc[mi][2 * nip + 1], ah[mi], bl1, bl3);
                MMA_BF16(acc[mi][2 * nip + 1], al[mi], bh1, bh3);
            }
        }
    }

    // ---- epilogue: BN + ReLU, write X[n][o] ----
    #pragma unroll
    for (int mi = 0; mi < 2; mi++) {
        int o0 = oB + oW + mi * 16 + r;              // rows o0 and o0+8
        float s0 = bn2w[o0] * rsqrtf(bn2v[o0] + EPS);
        float bi0 = bn2b[o0] - bn2m[o0] * s0;
        float s1 = bn2w[o0 + 8] * rsqrtf(bn2v[o0 + 8] + EPS);
        float bi1 = bn2b[o0 + 8] - bn2m[o0 + 8] * s1;
        #pragma unroll
        for (int ni = 0; ni < 8; ni++) {
            int n = nB + nW + ni * 8 + q2;
            Xo[(size_t)n * CH + o0]           = fmaxf(acc[mi][ni][0] * s0 + bi0, 0.f);
            Xo[(size_t)(n + 1) * CH + o0]     = fmaxf(acc[mi][ni][1] * s0 + bi0, 0.f);
            Xo[(size_t)n * CH + o0 + 8]       = fmaxf(acc[mi][ni][2] * s1 + bi1, 0.f);
            Xo[(size_t)(n + 1) * CH + o0 + 8] = fmaxf(acc[mi][ni][3] * s1 + bi1, 0.f);
        }
    }
}

// ---------------- K2: soft assignment + aggregation ----------------
__global__ __launch_bounds__(256) void k_encode(
    const float* __restrict__ codewords, const float* __restrict__ scale)
{
    const int b = blockIdx.y;
    const int n0 = blockIdx.x * 64;
    const float* Xg = g_X + (size_t)b * HW * CH + (size_t)n0 * CH;
    const int tid = threadIdx.x;

    __shared__ float Xs[64][68];    // 64-c chunk, padded
    __shared__ float cws[64][32];   // [c][k] chunk
    __shared__ float sls[64][33];
    __shared__ float Aw[64][32];    // softmax weights
    __shared__ float x2s[64];
    __shared__ float c2s[32];

    const int pix = tid >> 2;          // 0..63
    const int kg = (tid & 3) * 8;      // k base for xc
    float2 xc2[4];
    #pragma unroll
    for (int q = 0; q < 4; q++) xc2[q] = make_float2(0.f, 0.f);
    float x2acc = 0.f;
    float c2acc = 0.f;

    const int pr = tid >> 2, ccw = (tid & 3) * 16;
    const int kld = tid & 31, ccb = (tid >> 5) * 8;

    for (int c0 = 0; c0 < CH; c0 += 64) {
        #pragma unroll
        for (int q = 0; q < 4; q++)
            *(float4*)&Xs[pr][ccw + q * 4] =
                *(const float4*)&Xg[(size_t)pr * CH + c0 + ccw + q * 4];
        #pragma unroll
        for (int q = 0; q < 8; q++)
            cws[ccb + q][kld] = codewords[kld * CH + c0 + ccb + q];
        __syncthreads();

        if (tid < 32) {
            #pragma unroll 8
            for (int cc = 0; cc < 64; cc++) { float v = cws[cc][tid]; c2acc += v * v; }
        }
        #pragma unroll 4
        for (int cc = 0; cc < 64; cc++) {
            float xr = Xs[pix][cc];
            if ((tid & 3) == 0) x2acc += xr * xr;
            float2 xp = make_float2(xr, xr);
            float4 cv0 = *(const float4*)&cws[cc][kg];
            float4 cv1 = *(const float4*)&cws[cc][kg + 4];
            xc2[0] = ffma2(xp, make_float2(cv0.x, cv0.y), xc2[0]);
            xc2[1] = ffma2(xp, make_float2(cv0.z, cv0.w), xc2[1]);
            xc2[2] = ffma2(xp, make_float2(cv1.x, cv1.y), xc2[2]);
            xc2[3] = ffma2(xp, make_float2(cv1.z, cv1.w), xc2[3]);
        }
        __syncthreads();
    }

    if ((tid & 3) == 0) x2s[pix] = x2acc;
    if (tid < 32) c2s[tid] = c2acc;
    __syncthreads();

    {
        float x2v = x2s[pix];
        float xcv[8] = { xc2[0].x, xc2[0].y, xc2[1].x, xc2[1].y,
                         xc2[2].x, xc2[2].y, xc2[3].x, xc2[3].y };
        #pragma unroll
        for (int kk = 0; kk < 8; kk++) {
            int k = kg + kk;
            sls[pix][k] = scale[k] * (x2v - 2.f * xcv[kk] + c2s[k]);
        }
    }
    __syncthreads();

    // softmax per pixel (K=32)
    if (tid < 64) {
        float m = -1e30f;
        #pragma unroll
        for (int k = 0; k < 32; k++) m = fmaxf(m, sls[tid][k]);
        float s = 0.f;
        #pragma unroll
        for (int k = 0; k < 32; k++) {
            float e = expf(sls[tid][k] - m);
            Aw[tid][k] = e;
            s += e;
        }
        float inv = 1.f / s;
        #pragma unroll
        for (int k = 0; k < 32; k++) Aw[tid][k] *= inv;
    }
    __syncthreads();

    if (tid < 32) {
        float s = 0.f;
        #pragma unroll 8
        for (int p = 0; p < 64; p++) s += Aw[p][tid];
        atomicAdd(&g_Asum[b * KCODE + tid], s);
    }

    // G += A^T X  (per c-chunk)
    const int k4 = (tid & 7) * 4;
    const int dl = (tid >> 3) * 2;
    for (int c0 = 0; c0 < CH; c0 += 64) {
        __syncthreads();
        #pragma unroll
        for (int q = 0; q < 4; q++)
            *(float4*)&Xs[pr][ccw + q * 4] =
                *(const float4*)&Xg[(size_t)pr * CH + c0 + ccw + q * 4];
        __syncthreads();

        float2 acc[4];
        #pragma unroll
        for (int i = 0; i < 4; i++) acc[i] = make_float2(0.f, 0.f);
        #pragma unroll 4
        for (int p = 0; p < 64; p++) {
            float4 a4 = *(const float4*)&Aw[p][k4];
            float2 xv = *(const float2*)&Xs[p][dl];
            acc[0] = ffma2(make_float2(a4.x, a4.x), xv, acc[0]);
            acc[1] = ffma2(make_float2(a4.y, a4.y), xv, acc[1]);
            acc[2] = ffma2(make_float2(a4.z, a4.z), xv, acc[2]);
            acc[3] = ffma2(make_float2(a4.w, a4.w), xv, acc[3]);
        }
        #pragma unroll
        for (int i = 0; i < 4; i++) {
            float* gp = &g_G[((size_t)b * KCODE + k4 + i) * CH + c0 + dl];
            atomicAdd(gp, acc[i].x);
            atomicAdd(gp + 1, acc[i].y);
        }
    }
}

// ---------------- K3: E = G - Asum*cw, BN1 + ReLU, partial mean -> en ----------------
__global__ void k_en(const float* __restrict__ codewords,
                     const float* __restrict__ bn1w, const float* __restrict__ bn1b,
                     const float* __restrict__ bn1m, const float* __restrict__ bn1v)
{
    int idx = blockIdx.x * blockDim.x + threadIdx.x;
    if (idx >= 4 * BATCH * CH) return;
    int kq = idx >> 12;                 // 0..3
    int rem = idx & (BATCH * CH - 1);
    int b = rem >> 9, d = rem & 511;
    float acc = 0.f;
    #pragma unroll
    for (int kk = 0; kk < 8; kk++) {
        int k = kq * 8 + kk;
        float s1 = bn1w[k] * rsqrtf(bn1v[k] + EPS);
        float bias = bn1b[k] - bn1m[k] * s1;
        float e = g_G[((size_t)b * KCODE + k) * CH + d]
                - g_Asum[b * KCODE + k] * codewords[k * CH + d];
        acc += fmaxf(e * s1 + bias, 0.f);
    }
    atomicAdd(&g_en[rem], acc * (1.f / KCODE));
}

// ---------------- K4: gamma = sigmoid(en @ fc_w^T + fc_b); se head ----------------
__global__ __launch_bounds__(512) void k_gate(
    const float* __restrict__ fc_w, const float* __restrict__ fc_b,
    const float* __restrict__ se_w, const float* __restrict__ se_b,
    float* __restrict__ out_se)
{
    const int b = blockIdx.x;
    const int t = threadIdx.x;
    __shared__ float ens[CH];
    ens[t] = g_en[b * CH + t];
    __syncthreads();

    float acc = fc_b[t];
    const float* wr = fc_w + (size_t)t * CH;
    #pragma unroll 4
    for (int d = 0; d < CH; d += 4) {
        float4 w4 = *(const float4*)&wr[d];
        acc += ens[d] * w4.x + ens[d + 1] * w4.y + ens[d + 2] * w4.z + ens[d + 3] * w4.w;
    }
    g_gamma[b * CH + t] = 1.f / (1.f + expf(-acc));

    if (t < NCLASS) {
        float a2 = se_b[t];
        const float* sr = se_w + (size_t)t * CH;
        #pragma unroll 4
        for (int d = 0; d < CH; d += 4) {
            float4 w4 = *(const float4*)&sr[d];
            a2 += ens[d] * w4.x + ens[d + 1] * w4.y + ens[d + 2] * w4.z + ens[d + 3] * w4.w;
        }
        out_se[b * NCLASS + t] = a2;
    }
}

// ---------------- K5: out = relu(x * (1 + gamma)) ----------------
__global__ void k_out(const float* __restrict__ x, float* __restrict__ out)
{
    size_t i4 = (size_t)blockIdx.x * blockDim.x + threadIdx.x;   // float4 index
    size_t i = i4 * 4;
    int bc = (int)(i / HW);                 // b*CH + c (HW % 4 == 0, uniform per vec)
    float g = 1.f + g_gamma[bc];
    float4 v = ((const float4*)x)[i4];
    v.x = fmaxf(v.x * g, 0.f);
    v.y = fmaxf(v.y * g, 0.f);
    v.z = fmaxf(v.z * g, 0.f);
    v.w = fmaxf(v.w * g, 0.f);
    ((float4*)out)[i4] = v;
}

// ---------------- launch ----------------
extern "C" void kernel_launch(void* const* d_in, const int* in_sizes, int n_in,
                              void* d_out, int out_size)
{
    const float* x      = (const float*)d_in[0];
    const float* conv_w = (const float*)d_in[1];
    const float* bn2w   = (const float*)d_in[2];
    const float* bn2b   = (const float*)d_in[3];
    const float* bn2m   = (const float*)d_in[4];
    const float* bn2v   = (const float*)d_in[5];
    const float* cw     = (const float*)d_in[6];
    const float* scale  = (const float*)d_in[7];
    const float* bn1w   = (const float*)d_in[8];
    const float* bn1b   = (const float*)d_in[9];
    const float* bn1m   = (const float*)d_in[10];
    const float* bn1v   = (const float*)d_in[11];
    const float* fc_w   = (const float*)d_in[12];
    const float* fc_b   = (const float*)d_in[13];
    const float* se_w   = (const float*)d_in[14];
    const float* se_b   = (const float*)d_in[15];

    float* out_main = (float*)d_out;                                  // B*C*H*W
    float* out_se   = out_main + (size_t)BATCH * CH * HW;             // B*NCLASS

    k_zero<<<(BATCH * KCODE * CH + 255) / 256 + 1, 256>>>();

    k_prep_w<<<(CH * CH + 255) / 256, 256>>>(conv_w);

    dim3 gp(HW / 32, CH / 32, BATCH);
    k_prep_x<<<gp, 256>>>(x);

    dim3 g1(HW / 128, CH / 128, BATCH);
    k_conv<<<g1, 256>>>(bn2w, bn2b, bn2m, bn2v);

    dim3 g2(HW / 64, BATCH);
    k_encode<<<g2, 256>>>(cw, scale);

    k_en<<<(4 * BATCH * CH + 255) / 256, 256>>>(cw, bn1w, bn1b, bn1m, bn1v);

    k_gate<<<BATCH, 512>>>(fc_w, fc_b, se_w, se_b, out_se);

    size_t n4 = (size_t)BATCH * CH * HW / 4;
    k_out<<<(unsigned)(n4 / 256), 256>>>(x, out_main);
}

// round 17
// speedup vs baseline: 1.1029x; 1.0587x over previous
#include <cuda_runtime.h>
#include <cuda_bf16.h>
#include <cstdint>
#include <math.h>

#define BATCH 8
#define CH 512
#define HW 9216          // 96*96
#define KCODE 32
#define NCLASS 19
#define EPS 1e-5f

// ---------------- scratch (device globals; no allocation) ----------------
__device__ float g_X[(size_t)BATCH * HW * CH];   // (b, n, c) post conv+bn+relu
__device__ float g_G[BATCH * KCODE * CH];        // sum_n A[b,n,k] * X[b,n,c]
__device__ float g_Asum[BATCH * KCODE];
__device__ float g_en[BATCH * CH];
__device__ float g_gamma[BATCH * CH];
// pre-split bf16 hi/lo operands for the conv GEMM
__device__ unsigned short g_Whi[CH * CH], g_Wlo[CH * CH];                 // [o][c]
__device__ unsigned short g_Xthi[(size_t)BATCH * HW * CH];                // [b][n][c]
__device__ unsigned short g_Xtlo[(size_t)BATCH * HW * CH];

// ---------------- packed f32x2 FMA (sm_100+) ----------------
__device__ __forceinline__ float2 ffma2(float2 a, float2 b, float2 c) {
    unsigned long long ua = *(unsigned long long*)&a;
    unsigned long long ub = *(unsigned long long*)&b;
    unsigned long long uc = *(unsigned long long*)&c;
    unsigned long long ud;
    asm("fma.rn.f32x2 %0, %1, %2, %3;" : "=l"(ud) : "l"(ua), "l"(ub), "l"(uc));
    return *(float2*)&ud;
}

// bf16 mma m16n8k16, fp32 accumulate
#define MMA_BF16(d, a, b0_, b1_)                                            \
    asm volatile("mma.sync.aligned.m16n8k16.row.col.f32.bf16.bf16.f32 "     \
        "{%0,%1,%2,%3}, {%4,%5,%6,%7}, {%8,%9}, {%0,%1,%2,%3};"             \
        : "+f"((d)[0]), "+f"((d)[1]), "+f"((d)[2]), "+f"((d)[3])            \
        : "r"((a)[0]), "r"((a)[1]), "r"((a)[2]), "r"((a)[3]),               \
          "r"(b0_), "r"(b1_))

__device__ __forceinline__ void ldsm_x4(uint32_t& r0, uint32_t& r1,
                                        uint32_t& r2, uint32_t& r3, uint32_t addr) {
    asm volatile("ldmatrix.sync.aligned.m8n8.x4.shared.b16 {%0,%1,%2,%3}, [%4];"
        : "=r"(r0), "=r"(r1), "=r"(r2), "=r"(r3) : "r"(addr));
}

__device__ __forceinline__ void cp16(uint32_t smem_dst, const void* gsrc) {
    asm volatile("cp.async.cg.shared.global [%0], [%1], 16;"
        :: "r"(smem_dst), "l"(gsrc));
}
#define CP_COMMIT() asm volatile("cp.async.commit_group;")
#define CP_WAIT1()  asm volatile("cp.async.wait_group 1;")
#define CP_WAIT0()  asm volatile("cp.async.wait_group 0;")

// ---------------- K0: zero accumulators ----------------
__global__ void k_zero() {
    int i = blockIdx.x * blockDim.x + threadIdx.x;
    if (i < BATCH * KCODE * CH) g_G[i] = 0.f;
    if (i < BATCH * KCODE) g_Asum[i] = 0.f;
    if (i < BATCH * CH) g_en[i] = 0.f;
}

// ---------------- P1: split W -> hi/lo bf16 (once) ----------------
__global__ void k_prep_w(const float* __restrict__ W) {
    int i = blockIdx.x * blockDim.x + threadIdx.x;
    if (i >= CH * CH) return;
    float v = W[i];
    __nv_bfloat16 h = __float2bfloat16(v);
    g_Whi[i] = __bfloat16_as_ushort(h);
    g_Wlo[i] = __bfloat16_as_ushort(__float2bfloat16(v - __bfloat162float(h)));
}

// ---------------- P2: transpose + split x -> [b][n][c] hi/lo bf16 ----------------
__global__ __launch_bounds__(256) void k_prep_x(const float* __restrict__ x) {
    const int b = blockIdx.z;
    const int nB = blockIdx.x * 32;
    const int cB = blockIdx.y * 32;
    __shared__ float t[32][33];
    const int tx = threadIdx.x & 31, ty = threadIdx.x >> 5;   // ty 0..7
    const float* xb = x + (size_t)b * CH * HW;
    #pragma unroll
    for (int i = 0; i < 4; i++) {
        int c = cB + ty + i * 8;
        t[ty + i * 8][tx] = xb[(size_t)c * HW + nB + tx];
    }
    __syncthreads();
    unsigned short* oh = g_Xthi + (size_t)b * HW * CH;
    unsigned short* ol = g_Xtlo + (size_t)b * HW * CH;
    #pragma unroll
    for (int i = 0; i < 4; i++) {
        int n = nB + ty + i * 8;
        float v = t[tx][ty + i * 8];
        __nv_bfloat16 h = __float2bfloat16(v);
        size_t o = (size_t)n * CH + cB + tx;
        oh[o] = __bfloat16_as_ushort(h);
        ol[o] = __bfloat16_as_ushort(__float2bfloat16(v - __bfloat162float(h)));
    }
}

// ---------------- K1: conv(1x1), bf16 split mma, cp.async double-buffer ----------
// KC=32: half the barriers/wait_groups vs KC=16; dynamic smem 81,920B.
#define KC 32
#define SSTR 40   // halfword stride (80B): 16B-aligned rows, ldsm conflict-free
__global__ __launch_bounds__(256, 2) void k_conv(
    const float* __restrict__ bn2w, const float* __restrict__ bn2b,
    const float* __restrict__ bn2m, const float* __restrict__ bn2v)
{
    const int b = blockIdx.z;
    const unsigned short* Bxh = g_Xthi + (size_t)b * HW * CH;   // [n][c]
    const unsigned short* Bxl = g_Xtlo + (size_t)b * HW * CH;
    float* Xo = g_X + (size_t)b * HW * CH;                      // [n][o]
    const int oB = blockIdx.y * 128;
    const int nB = blockIdx.x * 128;

    extern __shared__ __align__(16) unsigned short dsm[];
    // layout: [Ah | Al | Bh | Bl], each 2 bufs x 128 x SSTR halfwords
    const uint32_t bufB = 128 * SSTR * 2;            // bytes per buffer
    const uint32_t matB = 2 * bufB;                  // bytes per matrix region
    uint32_t sBase = (uint32_t)__cvta_generic_to_shared(dsm);
    uint32_t sAh = sBase, sAl = sBase + matB, sBh = sBase + 2 * matB, sBl = sBase + 3 * matB;

    const int tid = threadIdx.x;
    const int lane = tid & 31, wid = tid >> 5;
    const int wm = wid >> 1, wn = wid & 1;          // warp grid 4x2
    const int oW = wm * 32, nW = wn * 64;
    const int r = lane >> 2, q2 = (lane & 3) * 2;
    const int lrow = lane & 15, lcol = (lane >> 4) * 8;   // ldmatrix lane mapping

    float acc[2][8][4];
    #pragma unroll
    for (int mi = 0; mi < 2; mi++)
        #pragma unroll
        for (int ni = 0; ni < 8; ni++)
            #pragma unroll
            for (int j = 0; j < 4; j++) acc[mi][ni][j] = 0.f;

    // staging: 128 rows x 32 halfs per matrix = 512 x 16B slots; 2 slots/thread
    #define STAGE(chunk, buf)                                                    \
        do {                                                                     \
            _Pragma("unroll")                                                    \
            for (int m_ = 0; m_ < 2; m_++) {                                     \
                int slot = tid + m_ * 256;                                       \
                int row = slot >> 2, q8 = (slot & 3) * 8;                        \
                int k0_ = (chunk) * KC + q8;                                     \
                uint32_t d_ = (buf) * bufB + (uint32_t)(row * SSTR + q8) * 2;    \
                cp16(sAh + d_, &g_Whi[(size_t)(oB + row) * CH + k0_]);           \
                cp16(sAl + d_, &g_Wlo[(size_t)(oB + row) * CH + k0_]);           \
                cp16(sBh + d_, &Bxh[(size_t)(nB + row) * CH + k0_]);             \
                cp16(sBl + d_, &Bxl[(size_t)(nB + row) * CH + k0_]);             \
            }                                                                    \
        } while (0)

    STAGE(0, 0);
    CP_COMMIT();

    for (int c = 0; c < CH / KC; c++) {
        __syncthreads();                  // prior compute on target buf done
        if (c + 1 < CH / KC) {
            STAGE(c + 1, (c + 1) & 1);
            CP_COMMIT();
            CP_WAIT1();
        } else {
            CP_WAIT0();
        }
        __syncthreads();                  // staged data visible to all warps

        const uint32_t bofs = (uint32_t)(c & 1) * bufB;
        #pragma unroll
        for (int s = 0; s < KC; s += 16) {
            uint32_t ah[2][4], al[2][4];
            #pragma unroll
            for (int mi = 0; mi < 2; mi++) {
                uint32_t aoff = bofs + (uint32_t)(((oW + mi * 16 + lrow) * SSTR + s + lcol) * 2);
                ldsm_x4(ah[mi][0], ah[mi][1], ah[mi][2], ah[mi][3], sAh + aoff);
                ldsm_x4(al[mi][0], al[mi][1], al[mi][2], al[mi][3], sAl + aoff);
            }
            #pragma unroll
            for (int nip = 0; nip < 4; nip++) {          // 2 n-tiles per ldsm.x4
                uint32_t boff = bofs + (uint32_t)(((nW + nip * 16 + lrow) * SSTR + s + lcol) * 2);
                uint32_t bh0, bh1, bh2, bh3, bl0, bl1, bl2, bl3;
                ldsm_x4(bh0, bh1, bh2, bh3, sBh + boff);
                ldsm_x4(bl0, bl1, bl2, bl3, sBl + boff);
                #pragma unroll
                for (int mi = 0; mi < 2; mi++) {
                    MMA_BF16(acc[mi][2 * nip],     ah[mi], bh0, bh2);
                    MMA_BF16(acc[mi][2 * nip],     ah[mi], bl0, bl2);
                    MMA_BF16(acc[mi][2 * nip],     al[mi], bh0, bh2);
                    MMA_BF16(acc[mi][2 * nip + 1], ah[mi], bh1, bh3);
                    MMA_BF16(acc[mi][2 * nip + 1], ah[mi], bl1, bl3);
                    MMA_BF16(acc[mi][2 * nip + 1], al[mi], bh1, bh3);
                }
            }
        }
    }

    // ---- epilogue: BN + ReLU, write X[n][o] ----
    #pragma unroll
    for (int mi = 0; mi < 2; mi++) {
        int o0 = oB + oW + mi * 16 + r;              // rows o0 and o0+8
        float s0 = bn2w[o0] * rsqrtf(bn2v[o0] + EPS);
        float bi0 = bn2b[o0] - bn2m[o0] * s0;
        float s1 = bn2w[o0 + 8] * rsqrtf(bn2v[o0 + 8] + EPS);
        float bi1 = bn2b[o0 + 8] - bn2m[o0 + 8] * s1;
        #pragma unroll
        for (int ni = 0; ni < 8; ni++) {
            int n = nB + nW + ni * 8 + q2;
            Xo[(size_t)n * CH + o0]           = fmaxf(acc[mi][ni][0] * s0 + bi0, 0.f);
            Xo[(size_t)(n + 1) * CH + o0]     = fmaxf(acc[mi][ni][1] * s0 + bi0, 0.f);
            Xo[(size_t)n * CH + o0 + 8]       = fmaxf(acc[mi][ni][2] * s1 + bi1, 0.f);
            Xo[(size_t)(n + 1) * CH + o0 + 8] = fmaxf(acc[mi][ni][3] * s1 + bi1, 0.f);
        }
    }
}

// ---------------- K2: soft assignment + aggregation ----------------
__global__ __launch_bounds__(256) void k_encode(
    const float* __restrict__ codewords, const float* __restrict__ scale)
{
    const int b = blockIdx.y;
    const int n0 = blockIdx.x * 64;
    const float* Xg = g_X + (size_t)b * HW * CH + (size_t)n0 * CH;
    const int tid = threadIdx.x;

    __shared__ float Xs[64][68];    // 64-c chunk, padded
    __shared__ float cws[64][32];   // [c][k] chunk
    __shared__ float sls[64][33];
    __shared__ float Aw[64][32];    // softmax weights
    __shared__ float x2s[64];
    __shared__ float c2s[32];

    const int pix = tid >> 2;          // 0..63
    const int kg = (tid & 3) * 8;      // k base for xc
    float2 xc2[4];
    #pragma unroll
    for (int q = 0; q < 4; q++) xc2[q] = make_float2(0.f, 0.f);
    float x2acc = 0.f;
    float c2acc = 0.f;

    const int pr = tid >> 2, ccw = (tid & 3) * 16;
    const int kld = tid & 31, ccb = (tid >> 5) * 8;

    for (int c0 = 0; c0 < CH; c0 += 64) {
        #pragma unroll
        for (int q = 0; q < 4; q++)
            *(float4*)&Xs[pr][ccw + q * 4] =
                *(const float4*)&Xg[(size_t)pr * CH + c0 + ccw + q * 4];
        #pragma unroll
        for (int q = 0; q < 8; q++)
            cws[ccb + q][kld] = codewords[kld * CH + c0 + ccb + q];
        __syncthreads();

        if (tid < 32) {
            #pragma unroll 8
            for (int cc = 0; cc < 64; cc++) { float v = cws[cc][tid]; c2acc += v * v; }
        }
        #pragma unroll 4
        for (int cc = 0; cc < 64; cc++) {
            float xr = Xs[pix][cc];
            if ((tid & 3) == 0) x2acc += xr * xr;
            float2 xp = make_float2(xr, xr);
            float4 cv0 = *(const float4*)&cws[cc][kg];
            float4 cv1 = *(const float4*)&cws[cc][kg + 4];
            xc2[0] = ffma2(xp, make_float2(cv0.x, cv0.y), xc2[0]);
            xc2[1] = ffma2(xp, make_float2(cv0.z, cv0.w), xc2[1]);
            xc2[2] = ffma2(xp, make_float2(cv1.x, cv1.y), xc2[2]);
            xc2[3] = ffma2(xp, make_float2(cv1.z, cv1.w), xc2[3]);
        }
        __syncthreads();
    }

    if ((tid & 3) == 0) x2s[pix] = x2acc;
    if (tid < 32) c2s[tid] = c2acc;
    __syncthreads();

    {
        float x2v = x2s[pix];
        float xcv[8] = { xc2[0].x, xc2[0].y, xc2[1].x, xc2[1].y,
                         xc2[2].x, xc2[2].y, xc2[3].x, xc2[3].y };
        #pragma unroll
        for (int kk = 0; kk < 8; kk++) {
            int k = kg + kk;
            sls[pix][k] = scale[k] * (x2v - 2.f * xcv[kk] + c2s[k]);
        }
    }
    __syncthreads();

    // softmax per pixel (K=32)
    if (tid < 64) {
        float m = -1e30f;
        #pragma unroll
        for (int k = 0; k < 32; k++) m = fmaxf(m, sls[tid][k]);
        float s = 0.f;
        #pragma unroll
        for (int k = 0; k < 32; k++) {
            float e = expf(sls[tid][k] - m);
            Aw[tid][k] = e;
            s += e;
        }
        float inv = 1.f / s;
        #pragma unroll
        for (int k = 0; k < 32; k++) Aw[tid][k] *= inv;
    }
    __syncthreads();

    if (tid < 32) {
        float s = 0.f;
        #pragma unroll 8
        for (int p = 0; p < 64; p++) s += Aw[p][tid];
        atomicAdd(&g_Asum[b * KCODE + tid], s);
    }

    // G += A^T X  (per c-chunk)
    const int k4 = (tid & 7) * 4;
    const int dl = (tid >> 3) * 2;
    for (int c0 = 0; c0 < CH; c0 += 64) {
        __syncthreads();
        #pragma unroll
        for (int q = 0; q < 4; q++)
            *(float4*)&Xs[pr][ccw + q * 4] =
                *(const float4*)&Xg[(size_t)pr * CH + c0 + ccw + q * 4];
        __syncthreads();

        float2 acc[4];
        #pragma unroll
        for (int i = 0; i < 4; i++) acc[i] = make_float2(0.f, 0.f);
        #pragma unroll 4
        for (int p = 0; p < 64; p++) {
            float4 a4 = *(const float4*)&Aw[p][k4];
            float2 xv = *(const float2*)&Xs[p][dl];
            acc[0] = ffma2(make_float2(a4.x, a4.x), xv, acc[0]);
            acc[1] = ffma2(make_float2(a4.y, a4.y), xv, acc[1]);
            acc[2] = ffma2(make_float2(a4.z, a4.z), xv, acc[2]);
            acc[3] = ffma2(make_float2(a4.w, a4.w), xv, acc[3]);
        }
        #pragma unroll
        for (int i = 0; i < 4; i++) {
            float* gp = &g_G[((size_t)b * KCODE + k4 + i) * CH + c0 + dl];
            atomicAdd(gp, acc[i].x);
            atomicAdd(gp + 1, acc[i].y);
        }
    }
}

// ---------------- K3: E = G - Asum*cw, BN1 + ReLU, partial mean -> en ----------------
__global__ void k_en(const float* __restrict__ codewords,
                     const float* __restrict__ bn1w, const float* __restrict__ bn1b,
                     const float* __restrict__ bn1m, const float* __restrict__ bn1v)
{
    int idx = blockIdx.x * blockDim.x + threadIdx.x;
    if (idx >= 4 * BATCH * CH) return;
    int kq = idx >> 12;                 // 0..3
    int rem = idx & (BATCH * CH - 1);
    int b = rem >> 9, d = rem & 511;
    float acc = 0.f;
    #pragma unroll
    for (int kk = 0; kk < 8; kk++) {
        int k = kq * 8 + kk;
        float s1 = bn1w[k] * rsqrtf(bn1v[k] + EPS);
        float bias = bn1b[k] - bn1m[k] * s1;
        float e = g_G[((size_t)b * KCODE + k) * CH + d]
                - g_Asum[b * KCODE + k] * codewords[k * CH + d];
        acc += fmaxf(e * s1 + bias, 0.f);
    }
    atomicAdd(&g_en[rem], acc * (1.f / KCODE));
}

// ---------------- K4: gamma = sigmoid(en @ fc_w^T + fc_b); se head ----------------
__global__ __launch_bounds__(512) void k_gate(
    const float* __restrict__ fc_w, const float* __restrict__ fc_b,
    const float* __restrict__ se_w, const float* __restrict__ se_b,
    float* __restrict__ out_se)
{
    const int b = blockIdx.x;
    const int t = threadIdx.x;
    __shared__ float ens[CH];
    ens[t] = g_en[b * CH + t];
    __syncthreads();

    float acc = fc_b[t];
    const float* wr = fc_w + (size_t)t * CH;
    #pragma unroll 4
    for (int d = 0; d < CH; d += 4) {
        float4 w4 = *(const float4*)&wr[d];
        acc += ens[d] * w4.x + ens[d + 1] * w4.y + ens[d + 2] * w4.z + ens[d + 3] * w4.w;
    }
    g_gamma[b * CH + t] = 1.f / (1.f + expf(-acc));

    if (t < NCLASS) {
        float a2 = se_b[t];
        const float* sr = se_w + (size_t)t * CH;
        #pragma unroll 4
        for (int d = 0; d < CH; d += 4) {
            float4 w4 = *(const float4*)&sr[d];
            a2 += ens[d] * w4.x + ens[d + 1] * w4.y + ens[d + 2] * w4.z + ens[d + 3] * w4.w;
        }
        out_se[b * NCLASS + t] = a2;
    }
}

// ---------------- K5: out = relu(x * (1 + gamma)) ----------------
__global__ void k_out(const float* __restrict__ x, float* __restrict__ out)
{
    size_t i4 = (size_t)blockIdx.x * blockDim.x + threadIdx.x;   // float4 index
    size_t i = i4 * 4;
    int bc = (int)(i / HW);                 // b*CH + c (HW % 4 == 0, uniform per vec)
    float g = 1.f + g_gamma[bc];
    float4 v = ((const float4*)x)[i4];
    v.x = fmaxf(v.x * g, 0.f);
    v.y = fmaxf(v.y * g, 0.f);
    v.z = fmaxf(v.z * g, 0.f);
    v.w = fmaxf(v.w * g, 0.f);
    ((float4*)out)[i4] = v;
}

// ---------------- launch ----------------
extern "C" void kernel_launch(void* const* d_in, const int* in_sizes, int n_in,
                              void* d_out, int out_size)
{
    const float* x      = (const float*)d_in[0];
    const float* conv_w = (const float*)d_in[1];
    const float* bn2w   = (const float*)d_in[2];
    const float* bn2b   = (const float*)d_in[3];
    const float* bn2m   = (const float*)d_in[4];
    const float* bn2v   = (const float*)d_in[5];
    const float* cw     = (const float*)d_in[6];
    const float* scale  = (const float*)d_in[7];
    const float* bn1w   = (const float*)d_in[8];
    const float* bn1b   = (const float*)d_in[9];
    const float* bn1m   = (const float*)d_in[10];
    const float* bn1v   = (const float*)d_in[11];
    const float* fc_w   = (const float*)d_in[12];
    const float* fc_b   = (const float*)d_in[13];
    const float* se_w   = (const float*)d_in[14];
    const float* se_b   = (const float*)d_in[15];

    float* out_main = (float*)d_out;                                  // B*C*H*W
    float* out_se   = out_main + (size_t)BATCH * CH * HW;             // B*NCLASS

    const int conv_smem = 4 * 2 * 128 * SSTR * 2;   // 81,920 B
    cudaFuncSetAttribute(k_conv, cudaFuncAttributeMaxDynamicSharedMemorySize, conv_smem);

    k_zero<<<(BATCH * KCODE * CH + 255) / 256 + 1, 256>>>();

    k_prep_w<<<(CH * CH + 255) / 256, 256>>>(conv_w);

    dim3 gp(HW / 32, CH / 32, BATCH);
    k_prep_x<<<gp, 256>>>(x);

    dim3 g1(HW / 128, CH / 128, BATCH);
    k_conv<<<g1, 256, conv_smem>>>(bn2w, bn2b, bn2m, bn2v);

    dim3 g2(HW / 64, BATCH);
    k_encode<<<g2, 256>>>(cw, scale);

    k_en<<<(4 * BATCH * CH + 255) / 256, 256>>>(cw, bn1w, bn1b, bn1m, bn1v);

    k_gate<<<BATCH, 512>>>(fc_w, fc_b, se_w, se_b, out_se);

    size_t n4 = (size_t)BATCH * CH * HW / 4;
    k_out<<<(unsigned)(n4 / 256), 256>>>(x, out_main);
}